// round 6
// baseline (speedup 1.0000x reference)
#include <cuda_runtime.h>

// QualityPredictorLoss — TERMINAL kernel.
//
// Proof of constant output: the reference computes
//   order = argsort(-sims); s = sims[order]         (s is non-increasing)
//   mask  = (g[:-1] < g[1:]) & (s[:-1] < s[1:])
// The conjunct s[i] < s[i+1] is unsatisfiable on a descending-sorted array
// (ties give equality, which also fails strict-less). Hence mask ≡ False and
// loss ≡ +0.0f for every input — independent of q_emb/d_embs/c_emb/rates.
// Verified empirically 5x: rel_err == 0.0 every run.
//
// Minimality: a correct capture must contain >=1 node that writes d_out.
// This graph is exactly one kernel node whose SASS body is {STG, EXIT}
// (grid=1, block=32, no index math, no predicate, broadcast store of the
// same value by all lanes — deterministic). R1-R5 measured kernel times
// {3.55, 4.67, 4.19, 3.49, 3.42} µs across bodies differing by <=3
// instructions, including two runs of THIS identical source differing by
// 0.32 µs e2e — remaining variation is harness replay jitter, not kernel
// behavior. Nothing left to optimize.

__global__ __launch_bounds__(32, 1)
void quality_predictor_loss_zero_kernel(float* __restrict__ out) {
    *out = 0.0f;
}

extern "C" void kernel_launch(void* const* d_in, const int* in_sizes, int n_in,
                              void* d_out, int out_size) {
    (void)d_in; (void)in_sizes; (void)n_in; (void)out_size;  // out_size == 1 (scalar loss)
    quality_predictor_loss_zero_kernel<<<1, 32>>>((float*)d_out);
}

// round 7
// speedup vs baseline: 1.0922x; 1.0922x over previous
#include <cuda_runtime.h>

// QualityPredictorLoss — TERMINAL kernel (held; bench samples noise only).
//
// Proof of constant output: the reference computes
//   order = argsort(-sims); s = sims[order]         (s is non-increasing)
//   mask  = (g[:-1] < g[1:]) & (s[:-1] < s[1:])
// The conjunct s[i] < s[i+1] is unsatisfiable on a descending-sorted array
// (ties give equality, which also fails strict-less). Hence mask ≡ False and
// loss ≡ +0.0f for every input — independent of q_emb/d_embs/c_emb/rates.
// Verified empirically 6x: rel_err == 0.0 every run.
//
// Minimality: a correct capture must contain >=1 node that writes d_out.
// This graph is exactly one kernel node whose SASS body is {STG, EXIT}.
// Byte-identical source has now been benched 3x: kernel time 3.45±0.04 µs
// (stable), e2e {4.86, 4.54, 4.93} µs (harness jitter ±0.4 µs). All pipes
// 0%, DRAM 0%. There is no node, instruction, or byte left to remove;
// any future e2e delta on this source is a noise draw by construction.

__global__ __launch_bounds__(32, 1)
void quality_predictor_loss_zero_kernel(float* __restrict__ out) {
    *out = 0.0f;
}

extern "C" void kernel_launch(void* const* d_in, const int* in_sizes, int n_in,
                              void* d_out, int out_size) {
    (void)d_in; (void)in_sizes; (void)n_in; (void)out_size;  // out_size == 1 (scalar loss)
    quality_predictor_loss_zero_kernel<<<1, 32>>>((float*)d_out);
}